// round 14
// baseline (speedup 1.0000x reference)
#include <cuda_runtime.h>
#include <cuda_fp16.h>
#include <cstdint>
#include <math.h>

typedef __half fp16;

#define BB  16
#define CC  512
#define HW  1024
#define GG  32
#define CPG 16
#define EPSV 1e-5f

// ---------------------------------------------------------------------------
// Scratch: pure fp16 tensors; scores fp16.
// ---------------------------------------------------------------------------
#define PL_W    ((size_t)2048*512)
#define PL_GN   ((size_t)BB*HW*512)
#define PL_Q    ((size_t)BB*HW*512)
#define PL_K    ((size_t)BB*HW*512)
#define PL_V    ((size_t)BB*CC*HW)
#define PL_ATT  ((size_t)BB*HW*HW)
#define PL_HH   ((size_t)BB*HW*512)
#define PL_S    ((size_t)BB*HW*HW)

#define OFF_WH   ((size_t)0)
#define OFF_GNH  (OFF_WH  + PL_W*2)
#define OFF_QH   (OFF_GNH + PL_GN*2)
#define OFF_KH   (OFF_QH  + PL_Q*2)
#define OFF_VH   (OFF_KH  + PL_K*2)
#define OFF_AH   (OFF_VH  + PL_V*2)
#define OFF_HHH  (OFF_AH  + PL_ATT*2)
#define OFF_S    (OFF_HHH + PL_HH*2)
#define SCRATCH_BYTES (OFF_S + PL_S*2)

__device__ __align__(256) unsigned char g_scratch[SCRATCH_BYTES];

// ---------------------------------------------------------------------------
// PTX helpers
// ---------------------------------------------------------------------------
__device__ __forceinline__ uint32_t smem_u32(const void* p) {
    uint32_t a;
    asm("{ .reg .u64 t; cvta.to.shared.u64 t, %1; cvt.u32.u64 %0, t; }" : "=r"(a) : "l"(p));
    return a;
}
__device__ __forceinline__ void ldsm4(uint32_t* r, uint32_t addr) {
    asm volatile("ldmatrix.sync.aligned.m8n8.x4.shared.b16 {%0,%1,%2,%3}, [%4];"
                 : "=r"(r[0]), "=r"(r[1]), "=r"(r[2]), "=r"(r[3]) : "r"(addr));
}
__device__ __forceinline__ void mma16816(float* d, const uint32_t* a, const uint32_t* b) {
    asm volatile("mma.sync.aligned.m16n8k16.row.col.f32.f16.f16.f32 "
        "{%0,%1,%2,%3}, {%4,%5,%6,%7}, {%8,%9}, {%0,%1,%2,%3};"
        : "+f"(d[0]), "+f"(d[1]), "+f"(d[2]), "+f"(d[3])
        : "r"(a[0]), "r"(a[1]), "r"(a[2]), "r"(a[3]), "r"(b[0]), "r"(b[1]));
}
__device__ __forceinline__ void cpasync16(uint32_t dst, const void* src) {
    asm volatile("cp.async.cg.shared.global [%0], [%1], 16;" :: "r"(dst), "l"(src));
}
#define CP_COMMIT() asm volatile("cp.async.commit_group;" ::: "memory")
#define CP_WAIT1()  asm volatile("cp.async.wait_group 1;" ::: "memory")
#define CP_WAIT0()  asm volatile("cp.async.wait_group 0;" ::: "memory")

__device__ __forceinline__ void storeH2(fp16* ph, float v0, float v1) {
    *(half2*)ph = __halves2half2(__float2half(v0), __float2half(v1));
}

// ---------------------------------------------------------------------------
// Weight conversion
// ---------------------------------------------------------------------------
__global__ __launch_bounds__(256) void convert_w_kernel(
    const float* __restrict__ Wq, const float* __restrict__ Wk,
    const float* __restrict__ Wv, const float* __restrict__ Wo,
    fp16* __restrict__ WH)
{
    int r = blockIdx.x;
    int tid = threadIdx.x;
    const float* src = (r < 512)  ? Wq + (size_t)r * 512
                     : (r < 1024) ? Wk + (size_t)(r-512) * 512
                     : (r < 1536) ? Wv + (size_t)(r-1024) * 512
                                  : Wo + (size_t)(r-1536) * 512;
    fp16* dh = WH + (size_t)r * 512;
    for (int k = tid; k < 512; k += 256) dh[k] = __float2half(src[k]);
}

// ---------------------------------------------------------------------------
// GroupNorm + SiLU -> gn plane [b][n][512]
// ---------------------------------------------------------------------------
__global__ __launch_bounds__(256) void gn_silu_kernel(
    const float* __restrict__ x, const float* __restrict__ gamma,
    const float* __restrict__ beta, fp16* __restrict__ gnH)
{
    int bg = blockIdx.x;
    int b = bg / GG, g = bg % GG;
    const float* xp = x + ((size_t)b*CC + g*CPG) * HW;
    int tid = threadIdx.x;

    float s = 0.f, ss = 0.f;
    for (int i = tid; i < CPG*HW; i += 256) {
        float v = xp[i];
        s += v; ss += v*v;
    }
    __shared__ float sh0[256], sh1[256];
    sh0[tid] = s; sh1[tid] = ss;
    __syncthreads();
    for (int o = 128; o > 0; o >>= 1) {
        if (tid < o) { sh0[tid] += sh0[tid+o]; sh1[tid] += sh1[tid+o]; }
        __syncthreads();
    }
    const float inv_n = 1.f / (float)(CPG*HW);
    float mean = sh0[0] * inv_n;
    float var  = sh1[0] * inv_n - mean*mean;
    float rstd = rsqrtf(var + EPSV);

    float gm[CPG], bt[CPG];
    #pragma unroll
    for (int cl = 0; cl < CPG; cl++) { gm[cl] = gamma[g*CPG+cl]; bt[cl] = beta[g*CPG+cl]; }

    for (int n = tid; n < HW; n += 256) {
        fp16* dh = gnH + ((size_t)b*HW + n) * 512 + g*CPG;
        #pragma unroll
        for (int cl = 0; cl < CPG; cl += 2) {
            float v0 = (xp[cl*HW + n]     - mean) * rstd * gm[cl]   + bt[cl];
            float v1 = (xp[(cl+1)*HW + n] - mean) * rstd * gm[cl+1] + bt[cl+1];
            v0 = v0 / (1.f + __expf(-v0));
            v1 = v1 / (1.f + __expf(-v1));
            storeH2(dh + cl, v0, v1);
        }
    }
}

// ---------------------------------------------------------------------------
// Warp-per-row softmax: 8 warps/block, 1 row/warp, shfl reductions only.
// ---------------------------------------------------------------------------
__global__ __launch_bounds__(256) void softmax_kernel(
    const fp16* __restrict__ s, fp16* __restrict__ aH)
{
    int w = threadIdx.x >> 5, lane = threadIdx.x & 31;
    size_t row = (size_t)blockIdx.x * 8 + w;
    const half2* sp = (const half2*)(s + row * HW);
    half2* ap = (half2*)(aH + row * HW);

    float2 v[16];
    float m = -1e30f;
    #pragma unroll
    for (int i = 0; i < 16; i++) {
        v[i] = __half22float2(sp[i*32 + lane]);
        m = fmaxf(m, fmaxf(v[i].x, v[i].y));
    }
    #pragma unroll
    for (int o = 16; o; o >>= 1) m = fmaxf(m, __shfl_xor_sync(0xffffffffu, m, o));

    float sum = 0.f;
    #pragma unroll
    for (int i = 0; i < 16; i++) {
        v[i].x = __expf(v[i].x - m);
        v[i].y = __expf(v[i].y - m);
        sum += v[i].x + v[i].y;
    }
    #pragma unroll
    for (int o = 16; o; o >>= 1) sum += __shfl_xor_sync(0xffffffffu, sum, o);
    float inv = 1.f / sum;

    #pragma unroll
    for (int i = 0; i < 16; i++)
        ap[i*32 + lane] = __floats2half2_rn(v[i].x * inv, v[i].y * inv);
}

// ---------------------------------------------------------------------------
// HMMA GEMM, pure fp16. CTA 256x128 (25% less L2 traffic/FLOP than 128x128),
// 8 warps (4m x 2n) of 64x64, 256 threads, 1 CTA/SM (144 KB smem), K-chunk
// 64, 3-stage cp.async pipeline with multistage tail scheduling + fragment
// double buffering. Static x-major grid.
// EPI: 0=QK  1=V  2=SCORES(fp16)  3=AV  4=OUT
// ---------------------------------------------------------------------------
#define KC       64
#define OPA      32768                 // A: 256 rows * 128 B
#define OPBB     16384                 // B: 128 rows * 128 B
#define STAGE_B  (OPA + OPBB)          // 48 KB
#define SMEM_BYTES (3*STAGE_B)         // 144 KB

__device__ __forceinline__ void load_stage(uint32_t dst, const fp16* Ap, const fp16* Bp,
                                           int Kb, int tid)
{
    #pragma unroll
    for (int it = 0; it < 8; it++) {
        int e   = it*256 + tid;        // 0..2047 (A: 256 rows x 8 groups)
        int row = e >> 3, grp = e & 7;
        uint32_t off = (uint32_t)(row*128 + ((grp ^ (row & 7)) << 4));
        cpasync16(dst + off, Ap + (size_t)row * Kb + grp*8);
    }
    #pragma unroll
    for (int it = 0; it < 4; it++) {
        int e   = it*256 + tid;        // 0..1023 (B: 128 rows x 8 groups)
        int row = e >> 3, grp = e & 7;
        uint32_t off = (uint32_t)(row*128 + ((grp ^ (row & 7)) << 4));
        cpasync16(dst + OPA + off, Bp + (size_t)row * Kb + grp*8);
    }
}

template<int EPI>
__global__ __launch_bounds__(256, 1) void hmma_gemm(
    const fp16* __restrict__ AH, size_t aStr,
    const fp16* __restrict__ BH, size_t bStr, int Kb,
    const float* __restrict__ bias, const float* __restrict__ bias2,
    const float* __restrict__ xres,
    float* __restrict__ fOut, fp16* __restrict__ oH, fp16* __restrict__ o2H,
    float scale)
{
    extern __shared__ char smem[];
    const uint32_t sbase = smem_u32(smem);
    const int tid  = threadIdx.x;
    const int lane = tid & 31, wid = tid >> 5;
    const int wm = wid >> 1, wn = wid & 1;        // 4m x 2n warps
    const int bz = blockIdx.z;
    const int m0 = blockIdx.y * 256, n0 = blockIdx.x * 128;

    const fp16* AHb = AH + bz*aStr + (size_t)m0 * Kb;
    const fp16* BHb = BH + bz*bStr + (size_t)n0 * Kb;

    const int nch = Kb >> 6;

    // ldmatrix per-thread geometry
    const int aR0 = wm*64 + (lane & 15);
    const int aGs = lane >> 4;
    const int bR0 = wn*64 + (lane & 7) + ((lane >> 4) & 1) * 8;
    const int bGs = (lane >> 3) & 1;

    float acc[4][8][4];
    #pragma unroll
    for (int i = 0; i < 4; i++)
        #pragma unroll
        for (int j = 0; j < 8; j++)
            #pragma unroll
            for (int c = 0; c < 4; c++) acc[i][j][c] = 0.f;

    uint32_t afr[2][4][4];
    uint32_t bfr[2][8][2];

    // fragment loader: buffer bf, stage bases ab (A) / bb (B), k16-group g
    auto frag_load = [&](int bf, uint32_t ab, uint32_t bb, int g) {
        uint32_t gA = (uint32_t)(g + aGs);
        uint32_t gB = (uint32_t)(g + bGs);
        #pragma unroll
        for (int mf = 0; mf < 4; mf++) {
            int r = aR0 + mf*16;
            ldsm4(afr[bf][mf], ab + (uint32_t)(r*128) + ((gA ^ (uint32_t)(r & 7)) << 4));
        }
        #pragma unroll
        for (int p = 0; p < 4; p++) {
            int r = bR0 + p*16;
            uint32_t rr[4];
            ldsm4(rr, bb + (uint32_t)(r*128) + ((gB ^ (uint32_t)(r & 7)) << 4));
            bfr[bf][2*p][0]   = rr[0]; bfr[bf][2*p][1]   = rr[1];
            bfr[bf][2*p+1][0] = rr[2]; bfr[bf][2*p+1][1] = rr[3];
        }
    };

    // prologue: chunks 0,1 in flight; chunk0 step-0 fragments preloaded
    load_stage(sbase,           AHb,      BHb,      Kb, tid);  CP_COMMIT();
    load_stage(sbase + STAGE_B, AHb + KC, BHb + KC, Kb, tid);  CP_COMMIT();
    CP_WAIT1();
    __syncthreads();
    frag_load(0, sbase, sbase + OPA, 0);

    int stage = 0;
    #pragma unroll 1
    for (int t = 0; t < nch; t++) {
        const uint32_t abase = sbase + stage*STAGE_B;
        const uint32_t bbase = abase + OPA;
        int sN = stage + 1; if (sN == 3) sN = 0;
        int s2 = stage + 2; if (s2 >= 3) s2 -= 3;

        #pragma unroll
        for (int step = 0; step < 4; step++) {
            int cur = step & 1, nxt = cur ^ 1;
            if (step == 0 && t + 2 < nch) {
                load_stage(sbase + s2*STAGE_B, AHb + (t+2)*KC, BHb + (t+2)*KC, Kb, tid);
                CP_COMMIT();
            }
            if (step < 3) {
                frag_load(nxt, abase, bbase, (step+1)*2);
            } else {
                // stage tail: wait for chunk t+1, barrier, prefetch its step 0
                if (t + 2 < nch) CP_WAIT1(); else CP_WAIT0();
                __syncthreads();
                if (t + 1 < nch) {
                    uint32_t nab = sbase + sN*STAGE_B;
                    frag_load(nxt, nab, nab + OPA, 0);
                }
            }
            #pragma unroll
            for (int mf = 0; mf < 4; mf++)
                #pragma unroll
                for (int nf = 0; nf < 8; nf++)
                    mma16816(acc[mf][nf], afr[cur][mf], bfr[cur][nf]);
        }
        stage = sN;
    }

    // ---------------- epilogue ----------------
    const int tr = lane >> 2;
    const int tc = (lane & 3) * 2;

    #pragma unroll
    for (int mf = 0; mf < 4; mf++) {
        #pragma unroll
        for (int half = 0; half < 2; half++) {
            int r = m0 + wm*64 + mf*16 + tr + half*8;
            #pragma unroll
            for (int nf = 0; nf < 8; nf++) {
                int c = n0 + wn*64 + nf*8 + tc;
                float d0 = acc[mf][nf][half*2 + 0];
                float d1 = acc[mf][nf][half*2 + 1];

                if (EPI == 0) {                 // QK: D[i][ch], ch<512 q else k
                    if (c < 512) {
                        d0 += bias[c]; d1 += bias[c+1];
                        size_t idx = ((size_t)bz*HW + r) * 512 + c;
                        storeH2(oH + idx, d0, d1);
                    } else {
                        d0 += bias2[c-512]; d1 += bias2[c-511];
                        size_t idx = ((size_t)bz*HW + r) * 512 + (c - 512);
                        storeH2(o2H + idx, d0, d1);
                    }
                } else if (EPI == 1) {          // V: D[ch][i]
                    float bb = bias[r];
                    size_t idx = ((size_t)bz*CC + r) * HW + c;
                    storeH2(oH + idx, d0+bb, d1+bb);
                } else if (EPI == 2) {          // scores fp16, * scale
                    size_t idx = ((size_t)bz*HW + r) * HW + c;
                    storeH2(oH + idx, d0*scale, d1*scale);
                } else if (EPI == 3) {          // AV: D[i][ch]
                    size_t idx = ((size_t)bz*HW + r) * 512 + c;
                    storeH2(oH + idx, d0, d1);
                } else {                        // OUT: + bias + residual
                    float bb = bias[r];
                    size_t off = ((size_t)bz*CC + r) * HW + c;
                    float2 xr = *(const float2*)(xres + off);
                    *(float2*)(fOut + off) = make_float2(d0+bb+xr.x, d1+bb+xr.y);
                }
            }
        }
    }
}

// ---------------------------------------------------------------------------
extern "C" void kernel_launch(void* const* d_in, const int* in_sizes, int n_in,
                              void* d_out, int out_size)
{
    const float* x     = (const float*)d_in[0];
    const float* Wq    = (const float*)d_in[1];
    const float* bq    = (const float*)d_in[2];
    const float* Wk    = (const float*)d_in[3];
    const float* bk    = (const float*)d_in[4];
    const float* Wv    = (const float*)d_in[5];
    const float* bv    = (const float*)d_in[6];
    const float* Wo    = (const float*)d_in[7];
    const float* bo    = (const float*)d_in[8];
    const float* gamma = (const float*)d_in[9];
    const float* beta  = (const float*)d_in[10];
    float* out = (float*)d_out;

    unsigned char* base = nullptr;
    cudaGetSymbolAddress((void**)&base, g_scratch);
    fp16*  WH  = (fp16*)(base + OFF_WH);
    fp16*  gnH = (fp16*)(base + OFF_GNH);
    fp16*  qH  = (fp16*)(base + OFF_QH);
    fp16*  kH  = (fp16*)(base + OFF_KH);
    fp16*  vH  = (fp16*)(base + OFF_VH);
    fp16*  aH  = (fp16*)(base + OFF_AH);
    fp16*  hhH = (fp16*)(base + OFF_HHH);
    fp16*  sH  = (fp16*)(base + OFF_S);

    cudaFuncSetAttribute(hmma_gemm<0>, cudaFuncAttributeMaxDynamicSharedMemorySize, SMEM_BYTES);
    cudaFuncSetAttribute(hmma_gemm<1>, cudaFuncAttributeMaxDynamicSharedMemorySize, SMEM_BYTES);
    cudaFuncSetAttribute(hmma_gemm<2>, cudaFuncAttributeMaxDynamicSharedMemorySize, SMEM_BYTES);
    cudaFuncSetAttribute(hmma_gemm<3>, cudaFuncAttributeMaxDynamicSharedMemorySize, SMEM_BYTES);
    cudaFuncSetAttribute(hmma_gemm<4>, cudaFuncAttributeMaxDynamicSharedMemorySize, SMEM_BYTES);

    const float scale = 1.0f / sqrtf((float)CC);
    const size_t PXS = (size_t)HW * 512;
    const size_t CHS = (size_t)CC * HW;

    convert_w_kernel<<<2048, 256>>>(Wq, Wk, Wv, Wo, WH);
    gn_silu_kernel<<<BB*GG, 256>>>(x, gamma, beta, gnH);

    // QK: M=1024 pixels (A=gn), N=1024 q|k rows (B=W), K=512
    hmma_gemm<0><<<dim3(8, 4, BB), 256, SMEM_BYTES>>>(
        gnH, PXS, WH, 0, 512, bq, bk, nullptr, nullptr, qH, kH, 0.f);

    // V: M=512 channels (A=Wv), N=1024 pixels (B=gn), K=512
    hmma_gemm<1><<<dim3(8, 2, BB), 256, SMEM_BYTES>>>(
        WH + (size_t)1024*512, 0, gnH, PXS, 512,
        bv, nullptr, nullptr, nullptr, vH, nullptr, 0.f);

    // scores: M=1024 i (A=q), N=1024 j (B=k), K=512 -> fp16 * scale
    hmma_gemm<2><<<dim3(8, 4, BB), 256, SMEM_BYTES>>>(
        qH, PXS, kH, PXS, 512, nullptr, nullptr, nullptr,
        nullptr, sH, nullptr, scale);

    softmax_kernel<<<BB*HW/8, 256>>>(sH, aH);

    // AV: M=1024 i (A=attn), N=512 ch (B=v), K=1024 -> hh
    hmma_gemm<3><<<dim3(4, 4, BB), 256, SMEM_BYTES>>>(
        aH, (size_t)HW*HW, vH, CHS, 1024, nullptr, nullptr, nullptr,
        nullptr, hhH, nullptr, 0.f);

    // OUT: M=512 ch (A=Wo), N=1024 i (B=hh), K=512, +bo +x
    hmma_gemm<4><<<dim3(8, 2, BB), 256, SMEM_BYTES>>>(
        WH + (size_t)1536*512, 0, hhH, PXS, 512,
        bo, nullptr, x, out, nullptr, nullptr, 0.f);
}

// round 15
// speedup vs baseline: 1.1237x; 1.1237x over previous
#include <cuda_runtime.h>
#include <cuda_fp16.h>
#include <cstdint>
#include <math.h>

typedef __half fp16;

#define BB  16
#define CC  512
#define HW  1024
#define GG  32
#define CPG 16
#define EPSV 1e-5f

// ---------------------------------------------------------------------------
// Scratch: pure fp16 tensors; scores fp16.
// ---------------------------------------------------------------------------
#define PL_W    ((size_t)2048*512)
#define PL_GN   ((size_t)BB*HW*512)
#define PL_Q    ((size_t)BB*HW*512)
#define PL_K    ((size_t)BB*HW*512)
#define PL_V    ((size_t)BB*CC*HW)
#define PL_ATT  ((size_t)BB*HW*HW)
#define PL_HH   ((size_t)BB*HW*512)
#define PL_S    ((size_t)BB*HW*HW)

#define OFF_WH   ((size_t)0)
#define OFF_GNH  (OFF_WH  + PL_W*2)
#define OFF_QH   (OFF_GNH + PL_GN*2)
#define OFF_KH   (OFF_QH  + PL_Q*2)
#define OFF_VH   (OFF_KH  + PL_K*2)
#define OFF_AH   (OFF_VH  + PL_V*2)
#define OFF_HHH  (OFF_AH  + PL_ATT*2)
#define OFF_S    (OFF_HHH + PL_HH*2)
#define SCRATCH_BYTES (OFF_S + PL_S*2)

__device__ __align__(256) unsigned char g_scratch[SCRATCH_BYTES];

// ---------------------------------------------------------------------------
// PTX helpers
// ---------------------------------------------------------------------------
__device__ __forceinline__ uint32_t smem_u32(const void* p) {
    uint32_t a;
    asm("{ .reg .u64 t; cvta.to.shared.u64 t, %1; cvt.u32.u64 %0, t; }" : "=r"(a) : "l"(p));
    return a;
}
__device__ __forceinline__ void ldsm4(uint32_t* r, uint32_t addr) {
    asm volatile("ldmatrix.sync.aligned.m8n8.x4.shared.b16 {%0,%1,%2,%3}, [%4];"
                 : "=r"(r[0]), "=r"(r[1]), "=r"(r[2]), "=r"(r[3]) : "r"(addr));
}
__device__ __forceinline__ void mma16816(float* d, const uint32_t* a, const uint32_t* b) {
    asm volatile("mma.sync.aligned.m16n8k16.row.col.f32.f16.f16.f32 "
        "{%0,%1,%2,%3}, {%4,%5,%6,%7}, {%8,%9}, {%0,%1,%2,%3};"
        : "+f"(d[0]), "+f"(d[1]), "+f"(d[2]), "+f"(d[3])
        : "r"(a[0]), "r"(a[1]), "r"(a[2]), "r"(a[3]), "r"(b[0]), "r"(b[1]));
}
__device__ __forceinline__ void cpasync16(uint32_t dst, const void* src) {
    asm volatile("cp.async.cg.shared.global [%0], [%1], 16;" :: "r"(dst), "l"(src));
}
#define CP_COMMIT() asm volatile("cp.async.commit_group;" ::: "memory")
#define CP_WAIT1()  asm volatile("cp.async.wait_group 1;" ::: "memory")
#define CP_WAIT0()  asm volatile("cp.async.wait_group 0;" ::: "memory")

__device__ __forceinline__ void storeH2(fp16* ph, float v0, float v1) {
    *(half2*)ph = __halves2half2(__float2half(v0), __float2half(v1));
}

// ---------------------------------------------------------------------------
// Weight conversion
// ---------------------------------------------------------------------------
__global__ __launch_bounds__(256) void convert_w_kernel(
    const float* __restrict__ Wq, const float* __restrict__ Wk,
    const float* __restrict__ Wv, const float* __restrict__ Wo,
    fp16* __restrict__ WH)
{
    int r = blockIdx.x;
    int tid = threadIdx.x;
    const float* src = (r < 512)  ? Wq + (size_t)r * 512
                     : (r < 1024) ? Wk + (size_t)(r-512) * 512
                     : (r < 1536) ? Wv + (size_t)(r-1024) * 512
                                  : Wo + (size_t)(r-1536) * 512;
    fp16* dh = WH + (size_t)r * 512;
    for (int k = tid; k < 512; k += 256) dh[k] = __float2half(src[k]);
}

// ---------------------------------------------------------------------------
// GroupNorm + SiLU -> gn plane [b][n][512]
// ---------------------------------------------------------------------------
__global__ __launch_bounds__(256) void gn_silu_kernel(
    const float* __restrict__ x, const float* __restrict__ gamma,
    const float* __restrict__ beta, fp16* __restrict__ gnH)
{
    int bg = blockIdx.x;
    int b = bg / GG, g = bg % GG;
    const float* xp = x + ((size_t)b*CC + g*CPG) * HW;
    int tid = threadIdx.x;

    float s = 0.f, ss = 0.f;
    for (int i = tid; i < CPG*HW; i += 256) {
        float v = xp[i];
        s += v; ss += v*v;
    }
    __shared__ float sh0[256], sh1[256];
    sh0[tid] = s; sh1[tid] = ss;
    __syncthreads();
    for (int o = 128; o > 0; o >>= 1) {
        if (tid < o) { sh0[tid] += sh0[tid+o]; sh1[tid] += sh1[tid+o]; }
        __syncthreads();
    }
    const float inv_n = 1.f / (float)(CPG*HW);
    float mean = sh0[0] * inv_n;
    float var  = sh1[0] * inv_n - mean*mean;
    float rstd = rsqrtf(var + EPSV);

    float gm[CPG], bt[CPG];
    #pragma unroll
    for (int cl = 0; cl < CPG; cl++) { gm[cl] = gamma[g*CPG+cl]; bt[cl] = beta[g*CPG+cl]; }

    for (int n = tid; n < HW; n += 256) {
        fp16* dh = gnH + ((size_t)b*HW + n) * 512 + g*CPG;
        #pragma unroll
        for (int cl = 0; cl < CPG; cl += 2) {
            float v0 = (xp[cl*HW + n]     - mean) * rstd * gm[cl]   + bt[cl];
            float v1 = (xp[(cl+1)*HW + n] - mean) * rstd * gm[cl+1] + bt[cl+1];
            v0 = v0 / (1.f + __expf(-v0));
            v1 = v1 / (1.f + __expf(-v1));
            storeH2(dh + cl, v0, v1);
        }
    }
}

// ---------------------------------------------------------------------------
// Warp-per-row softmax: 8 warps/block, 1 row/warp, shfl reductions only.
// ---------------------------------------------------------------------------
__global__ __launch_bounds__(256) void softmax_kernel(
    const fp16* __restrict__ s, fp16* __restrict__ aH)
{
    int w = threadIdx.x >> 5, lane = threadIdx.x & 31;
    size_t row = (size_t)blockIdx.x * 8 + w;
    const half2* sp = (const half2*)(s + row * HW);
    half2* ap = (half2*)(aH + row * HW);

    float2 v[16];
    float m = -1e30f;
    #pragma unroll
    for (int i = 0; i < 16; i++) {
        v[i] = __half22float2(sp[i*32 + lane]);
        m = fmaxf(m, fmaxf(v[i].x, v[i].y));
    }
    #pragma unroll
    for (int o = 16; o; o >>= 1) m = fmaxf(m, __shfl_xor_sync(0xffffffffu, m, o));

    float sum = 0.f;
    #pragma unroll
    for (int i = 0; i < 16; i++) {
        v[i].x = __expf(v[i].x - m);
        v[i].y = __expf(v[i].y - m);
        sum += v[i].x + v[i].y;
    }
    #pragma unroll
    for (int o = 16; o; o >>= 1) sum += __shfl_xor_sync(0xffffffffu, sum, o);
    float inv = 1.f / sum;

    #pragma unroll
    for (int i = 0; i < 16; i++)
        ap[i*32 + lane] = __floats2half2_rn(v[i].x * inv, v[i].y * inv);
}

// ---------------------------------------------------------------------------
// HMMA GEMM, pure fp16. CTA 128x128, 4 warps (2x2), warp tile 64x64, K-chunk
// 64, 3-stage cp.async pipeline with multistage tail scheduling + fragment
// double buffering, STATIC PERSISTENT TILE CHAINING: each CTA processes
// tiles bx, bx+G, bx+2G... with the chunk stream crossing tile boundaries
// (one prologue per CTA, not per tile). All addressing pow2 (shifts only).
// EPI: 0=QK  1=V  2=SCORES(fp16)  3=AV  4=OUT
// ---------------------------------------------------------------------------
#define KC       64
#define OPB      16384
#define STAGE_B  (2*OPB)
#define SMEM_BYTES (3*STAGE_B)
#define NPERS    296

template<int LOG_NCH>
__device__ __forceinline__ void load_stage(uint32_t dst, const fp16* Ap, const fp16* Bp,
                                           int tid)
{
    constexpr int Kb = KC << LOG_NCH;
    #pragma unroll
    for (int it = 0; it < 8; it++) {
        int e   = it*128 + tid;
        int row = e >> 3, grp = e & 7;
        uint32_t off = (uint32_t)(row*128 + ((grp ^ (row & 7)) << 4));
        cpasync16(dst + off,       Ap + (size_t)row * Kb + grp*8);
        cpasync16(dst + OPB + off, Bp + (size_t)row * Kb + grp*8);
    }
}

// EPI, log2(nch), log2(ntn), log2(per_b)
template<int EPI, int LOG_NCH, int LOG_NTN, int LOG_PERB>
__global__ __launch_bounds__(128, 2) void hmma_gemm(
    const fp16* __restrict__ AH, size_t aStr,
    const fp16* __restrict__ BH, size_t bStr,
    const float* __restrict__ bias, const float* __restrict__ bias2,
    const float* __restrict__ xres,
    float* __restrict__ fOut, fp16* __restrict__ oH, fp16* __restrict__ o2H,
    float scale, int ntiles)
{
    constexpr int nch = 1 << LOG_NCH;
    constexpr int Kb  = KC << LOG_NCH;
    extern __shared__ char smem[];
    const uint32_t sbase = smem_u32(smem);
    const int tid  = threadIdx.x;
    const int lane = tid & 31, wid = tid >> 5;
    const int wm = wid >> 1, wn = wid & 1;
    const int bx = blockIdx.x;
    const int G  = (int)gridDim.x;

    const int my_n = (bx < ntiles) ? ((ntiles - 1 - bx) / G + 1) : 0;
    if (my_n == 0) return;
    const int total = my_n << LOG_NCH;

    // pow2 tile -> pointer helpers
    auto tileA = [&](int tile) -> const fp16* {
        int bz  = tile >> LOG_PERB;
        int rem = tile & ((1 << LOG_PERB) - 1);
        int m0  = (rem >> LOG_NTN) << 7;
        return AH + (size_t)bz*aStr + (size_t)m0 * Kb;
    };
    auto tileB = [&](int tile) -> const fp16* {
        int bz  = tile >> LOG_PERB;
        int rem = tile & ((1 << LOG_PERB) - 1);
        int n0  = (rem & ((1 << LOG_NTN) - 1)) << 7;
        return BH + (size_t)bz*bStr + (size_t)n0 * Kb;
    };

    // ldmatrix per-thread geometry
    const int aR0 = wm*64 + (lane & 15);
    const int aGs = lane >> 4;
    const int bR0 = wn*64 + (lane & 7) + ((lane >> 4) & 1) * 8;
    const int bGs = (lane >> 3) & 1;

    float acc[4][8][4];
    #pragma unroll
    for (int i = 0; i < 4; i++)
        #pragma unroll
        for (int j = 0; j < 8; j++)
            #pragma unroll
            for (int c = 0; c < 4; c++) acc[i][j][c] = 0.f;

    uint32_t afr[2][4][4];
    uint32_t bfr[2][8][2];

    auto frag_load = [&](int bf, uint32_t ab, uint32_t bb, int g) {
        uint32_t gA = (uint32_t)(g + aGs);
        uint32_t gB = (uint32_t)(g + bGs);
        #pragma unroll
        for (int mf = 0; mf < 4; mf++) {
            int r = aR0 + mf*16;
            ldsm4(afr[bf][mf], ab + (uint32_t)(r*128) + ((gA ^ (uint32_t)(r & 7)) << 4));
        }
        #pragma unroll
        for (int p = 0; p < 4; p++) {
            int r = bR0 + p*16;
            uint32_t rr[4];
            ldsm4(rr, bb + (uint32_t)(r*128) + ((gB ^ (uint32_t)(r & 7)) << 4));
            bfr[bf][2*p][0]   = rr[0]; bfr[bf][2*p][1]   = rr[1];
            bfr[bf][2*p+1][0] = rr[2]; bfr[bf][2*p+1][1] = rr[3];
        }
    };

    // current tile pointers
    const fp16* Ac = tileA(bx);
    const fp16* Bc = tileB(bx);

    // prologue: global chunks 0,1 (both in tile 0 since nch >= 8)
    load_stage<LOG_NCH>(sbase,           Ac,      Bc,      tid);  CP_COMMIT();
    load_stage<LOG_NCH>(sbase + STAGE_B, Ac + KC, Bc + KC, tid);  CP_COMMIT();
    CP_WAIT1();
    __syncthreads();
    frag_load(0, sbase, sbase + OPB, 0);

    int stage = 0;
    #pragma unroll 1
    for (int i = 0; i < my_n; i++) {
        const int tile = bx + i*G;
        #pragma unroll 1
        for (int t = 0; t < nch; t++) {
            const int g = (i << LOG_NCH) + t;
            const uint32_t abase = sbase + stage*STAGE_B;
            const uint32_t bbase = abase + OPB;
            int sN = stage + 1; if (sN == 3) sN = 0;
            int s2 = stage + 2; if (s2 >= 3) s2 -= 3;

            #pragma unroll
            for (int step = 0; step < 4; step++) {
                int cur = step & 1, nxt = cur ^ 1;
                if (step == 0 && g + 2 < total) {
                    int gp = g + 2;
                    int ip = gp >> LOG_NCH;
                    int cp = gp & (nch - 1);
                    const fp16* Ap; const fp16* Bp;
                    if (ip == i) { Ap = Ac + cp*KC; Bp = Bc + cp*KC; }
                    else {
                        int tl = bx + ip*G;
                        Ap = tileA(tl) + cp*KC;
                        Bp = tileB(tl) + cp*KC;
                    }
                    load_stage<LOG_NCH>(sbase + s2*STAGE_B, Ap, Bp, tid);
                    CP_COMMIT();
                }
                if (step < 3) {
                    frag_load(nxt, abase, bbase, (step+1)*2);
                } else {
                    if (g + 2 < total) CP_WAIT1(); else CP_WAIT0();
                    __syncthreads();
                    if (g + 1 < total) {
                        uint32_t nab = sbase + sN*STAGE_B;
                        frag_load(nxt, nab, nab + OPB, 0);
                    }
                }
                #pragma unroll
                for (int mf = 0; mf < 4; mf++)
                    #pragma unroll
                    for (int nf = 0; nf < 8; nf++)
                        mma16816(acc[mf][nf], afr[cur][mf], bfr[cur][nf]);
            }
            stage = sN;
        }

        // ---------------- epilogue for tile ----------------
        {
            int bz  = tile >> LOG_PERB;
            int rem = tile & ((1 << LOG_PERB) - 1);
            int m0  = (rem >> LOG_NTN) << 7;
            int n0  = (rem & ((1 << LOG_NTN) - 1)) << 7;
            const int tr = lane >> 2;
            const int tc = (lane & 3) * 2;

            #pragma unroll
            for (int mf = 0; mf < 4; mf++) {
                #pragma unroll
                for (int half = 0; half < 2; half++) {
                    int r = m0 + wm*64 + mf*16 + tr + half*8;
                    #pragma unroll
                    for (int nf = 0; nf < 8; nf++) {
                        int c = n0 + wn*64 + nf*8 + tc;
                        float d0 = acc[mf][nf][half*2 + 0];
                        float d1 = acc[mf][nf][half*2 + 1];

                        if (EPI == 0) {                 // QK
                            if (c < 512) {
                                d0 += bias[c]; d1 += bias[c+1];
                                size_t idx = ((size_t)bz*HW + r) * 512 + c;
                                storeH2(oH + idx, d0, d1);
                            } else {
                                d0 += bias2[c-512]; d1 += bias2[c-511];
                                size_t idx = ((size_t)bz*HW + r) * 512 + (c - 512);
                                storeH2(o2H + idx, d0, d1);
                            }
                        } else if (EPI == 1) {          // V: D[ch][i]
                            float bb = bias[r];
                            size_t idx = ((size_t)bz*CC + r) * HW + c;
                            storeH2(oH + idx, d0+bb, d1+bb);
                        } else if (EPI == 2) {          // scores fp16, * scale
                            size_t idx = ((size_t)bz*HW + r) * HW + c;
                            storeH2(oH + idx, d0*scale, d1*scale);
                        } else if (EPI == 3) {          // AV
                            size_t idx = ((size_t)bz*HW + r) * 512 + c;
                            storeH2(oH + idx, d0, d1);
                        } else {                        // OUT: + bias + residual
                            float bb = bias[r];
                            size_t off = ((size_t)bz*CC + r) * HW + c;
                            float2 xr = *(const float2*)(xres + off);
                            *(float2*)(fOut + off) = make_float2(d0+bb+xr.x, d1+bb+xr.y);
                        }
                    }
                }
            }
            #pragma unroll
            for (int ii = 0; ii < 4; ii++)
                #pragma unroll
                for (int jj = 0; jj < 8; jj++)
                    #pragma unroll
                    for (int cc = 0; cc < 4; cc++) acc[ii][jj][cc] = 0.f;
        }

        if (i + 1 < my_n) {
            Ac = tileA(bx + (i+1)*G);
            Bc = tileB(bx + (i+1)*G);
        }
    }
}

// ---------------------------------------------------------------------------
extern "C" void kernel_launch(void* const* d_in, const int* in_sizes, int n_in,
                              void* d_out, int out_size)
{
    const float* x     = (const float*)d_in[0];
    const float* Wq    = (const float*)d_in[1];
    const float* bq    = (const float*)d_in[2];
    const float* Wk    = (const float*)d_in[3];
    const float* bk    = (const float*)d_in[4];
    const float* Wv    = (const float*)d_in[5];
    const float* bv    = (const float*)d_in[6];
    const float* Wo    = (const float*)d_in[7];
    const float* bo    = (const float*)d_in[8];
    const float* gamma = (const float*)d_in[9];
    const float* beta  = (const float*)d_in[10];
    float* out = (float*)d_out;

    unsigned char* base = nullptr;
    cudaGetSymbolAddress((void**)&base, g_scratch);
    fp16*  WH  = (fp16*)(base + OFF_WH);
    fp16*  gnH = (fp16*)(base + OFF_GNH);
    fp16*  qH  = (fp16*)(base + OFF_QH);
    fp16*  kH  = (fp16*)(base + OFF_KH);
    fp16*  vH  = (fp16*)(base + OFF_VH);
    fp16*  aH  = (fp16*)(base + OFF_AH);
    fp16*  hhH = (fp16*)(base + OFF_HHH);
    fp16*  sH  = (fp16*)(base + OFF_S);

    cudaFuncSetAttribute((const void*)hmma_gemm<0,3,3,6>, cudaFuncAttributeMaxDynamicSharedMemorySize, SMEM_BYTES);
    cudaFuncSetAttribute((const void*)hmma_gemm<1,3,3,5>, cudaFuncAttributeMaxDynamicSharedMemorySize, SMEM_BYTES);
    cudaFuncSetAttribute((const void*)hmma_gemm<2,3,3,6>, cudaFuncAttributeMaxDynamicSharedMemorySize, SMEM_BYTES);
    cudaFuncSetAttribute((const void*)hmma_gemm<3,4,2,5>, cudaFuncAttributeMaxDynamicSharedMemorySize, SMEM_BYTES);
    cudaFuncSetAttribute((const void*)hmma_gemm<4,3,3,5>, cudaFuncAttributeMaxDynamicSharedMemorySize, SMEM_BYTES);

    const float scale = 1.0f / sqrtf((float)CC);
    const size_t PXS = (size_t)HW * 512;
    const size_t CHS = (size_t)CC * HW;

    convert_w_kernel<<<2048, 256>>>(Wq, Wk, Wv, Wo, WH);
    gn_silu_kernel<<<BB*GG, 256>>>(x, gamma, beta, gnH);

    // QK: M=1024 pixels (A=gn), N=1024 q|k rows (B=W), K=512.
    // nch=8(log3), ntn=8(log3), per_b=64(log6), ntiles=1024.
    hmma_gemm<0,3,3,6><<<NPERS, 128, SMEM_BYTES>>>(
        gnH, PXS, WH, 0, bq, bk, nullptr, nullptr, qH, kH, 0.f, 64*BB);

    // V: M=512 ch (A=Wv), N=1024 px (B=gn), K=512. ntn=8, per_b=32(log5), 512 tiles.
    hmma_gemm<1,3,3,5><<<NPERS, 128, SMEM_BYTES>>>(
        WH + (size_t)1024*512, 0, gnH, PXS, bv, nullptr, nullptr,
        nullptr, vH, nullptr, 0.f, 32*BB);

    // scores: M=1024 i (A=q), N=1024 j (B=k), K=512 -> fp16 * scale. 1024 tiles.
    hmma_gemm<2,3,3,6><<<NPERS, 128, SMEM_BYTES>>>(
        qH, PXS, kH, PXS, nullptr, nullptr, nullptr,
        nullptr, sH, nullptr, scale, 64*BB);

    softmax_kernel<<<BB*HW/8, 256>>>(sH, aH);

    // AV: M=1024 i (A=attn), N=512 ch (B=v), K=1024. nch=16(log4), ntn=4(log2),
    // per_b=32(log5), 512 tiles.
    hmma_gemm<3,4,2,5><<<NPERS, 128, SMEM_BYTES>>>(
        aH, (size_t)HW*HW, vH, CHS, nullptr, nullptr, nullptr,
        nullptr, hhH, nullptr, 0.f, 32*BB);

    // OUT: M=512 ch (A=Wo), N=1024 i (B=hh), K=512, +bo +x. 512 tiles.
    hmma_gemm<4,3,3,5><<<NPERS, 128, SMEM_BYTES>>>(
        WH + (size_t)1536*512, 0, hhH, PXS, bo, nullptr, x,
        out, nullptr, nullptr, 0.f, 32*BB);
}

// round 16
// speedup vs baseline: 1.1467x; 1.0205x over previous
#include <cuda_runtime.h>
#include <cuda_fp16.h>
#include <cstdint>
#include <math.h>

typedef __half fp16;

#define BB  16
#define CC  512
#define HW  1024
#define GG  32
#define CPG 16
#define EPSV 1e-5f

// ---------------------------------------------------------------------------
// Scratch: pure fp16 tensors; attn buffer holds unnormalized exp(scores).
// ---------------------------------------------------------------------------
#define PL_W    ((size_t)2048*512)
#define PL_GN   ((size_t)BB*HW*512)
#define PL_Q    ((size_t)BB*HW*512)
#define PL_K    ((size_t)BB*HW*512)
#define PL_V    ((size_t)BB*CC*HW)
#define PL_ATT  ((size_t)BB*HW*HW)
#define PL_HH   ((size_t)BB*HW*512)

#define OFF_WH   ((size_t)0)
#define OFF_GNH  (OFF_WH  + PL_W*2)
#define OFF_QH   (OFF_GNH + PL_GN*2)
#define OFF_KH   (OFF_QH  + PL_Q*2)
#define OFF_VH   (OFF_KH  + PL_K*2)
#define OFF_AH   (OFF_VH  + PL_V*2)
#define OFF_HHH  (OFF_AH  + PL_ATT*2)
#define OFF_L    (OFF_HHH + PL_HH*2)
#define SCRATCH_BYTES (OFF_L + (size_t)BB*HW*4)

__device__ __align__(256) unsigned char g_scratch[SCRATCH_BYTES];

// ---------------------------------------------------------------------------
// PTX helpers
// ---------------------------------------------------------------------------
__device__ __forceinline__ uint32_t smem_u32(const void* p) {
    uint32_t a;
    asm("{ .reg .u64 t; cvta.to.shared.u64 t, %1; cvt.u32.u64 %0, t; }" : "=r"(a) : "l"(p));
    return a;
}
__device__ __forceinline__ void ldsm4(uint32_t* r, uint32_t addr) {
    asm volatile("ldmatrix.sync.aligned.m8n8.x4.shared.b16 {%0,%1,%2,%3}, [%4];"
                 : "=r"(r[0]), "=r"(r[1]), "=r"(r[2]), "=r"(r[3]) : "r"(addr));
}
__device__ __forceinline__ void mma16816(float* d, const uint32_t* a, const uint32_t* b) {
    asm volatile("mma.sync.aligned.m16n8k16.row.col.f32.f16.f16.f32 "
        "{%0,%1,%2,%3}, {%4,%5,%6,%7}, {%8,%9}, {%0,%1,%2,%3};"
        : "+f"(d[0]), "+f"(d[1]), "+f"(d[2]), "+f"(d[3])
        : "r"(a[0]), "r"(a[1]), "r"(a[2]), "r"(a[3]), "r"(b[0]), "r"(b[1]));
}
__device__ __forceinline__ void cpasync16(uint32_t dst, const void* src) {
    asm volatile("cp.async.cg.shared.global [%0], [%1], 16;" :: "r"(dst), "l"(src));
}
#define CP_COMMIT() asm volatile("cp.async.commit_group;" ::: "memory")
#define CP_WAIT1()  asm volatile("cp.async.wait_group 1;" ::: "memory")
#define CP_WAIT0()  asm volatile("cp.async.wait_group 0;" ::: "memory")

__device__ __forceinline__ void storeH2(fp16* ph, float v0, float v1) {
    *(half2*)ph = __halves2half2(__float2half(v0), __float2half(v1));
}
__device__ __forceinline__ float ex2(float x) {
    float r;
    asm("ex2.approx.ftz.f32 %0, %1;" : "=f"(r) : "f"(x));
    return r;
}

// ---------------------------------------------------------------------------
// Weight conversion
// ---------------------------------------------------------------------------
__global__ __launch_bounds__(256) void convert_w_kernel(
    const float* __restrict__ Wq, const float* __restrict__ Wk,
    const float* __restrict__ Wv, const float* __restrict__ Wo,
    fp16* __restrict__ WH)
{
    int r = blockIdx.x;
    int tid = threadIdx.x;
    const float* src = (r < 512)  ? Wq + (size_t)r * 512
                     : (r < 1024) ? Wk + (size_t)(r-512) * 512
                     : (r < 1536) ? Wv + (size_t)(r-1024) * 512
                                  : Wo + (size_t)(r-1536) * 512;
    fp16* dh = WH + (size_t)r * 512;
    for (int k = tid; k < 512; k += 256) dh[k] = __float2half(src[k]);
}

// ---------------------------------------------------------------------------
// GroupNorm + SiLU -> gn plane [b][n][512]
// ---------------------------------------------------------------------------
__global__ __launch_bounds__(256) void gn_silu_kernel(
    const float* __restrict__ x, const float* __restrict__ gamma,
    const float* __restrict__ beta, fp16* __restrict__ gnH)
{
    int bg = blockIdx.x;
    int b = bg / GG, g = bg % GG;
    const float* xp = x + ((size_t)b*CC + g*CPG) * HW;
    int tid = threadIdx.x;

    float s = 0.f, ss = 0.f;
    for (int i = tid; i < CPG*HW; i += 256) {
        float v = xp[i];
        s += v; ss += v*v;
    }
    __shared__ float sh0[256], sh1[256];
    sh0[tid] = s; sh1[tid] = ss;
    __syncthreads();
    for (int o = 128; o > 0; o >>= 1) {
        if (tid < o) { sh0[tid] += sh0[tid+o]; sh1[tid] += sh1[tid+o]; }
        __syncthreads();
    }
    const float inv_n = 1.f / (float)(CPG*HW);
    float mean = sh0[0] * inv_n;
    float var  = sh1[0] * inv_n - mean*mean;
    float rstd = rsqrtf(var + EPSV);

    float gm[CPG], bt[CPG];
    #pragma unroll
    for (int cl = 0; cl < CPG; cl++) { gm[cl] = gamma[g*CPG+cl]; bt[cl] = beta[g*CPG+cl]; }

    for (int n = tid; n < HW; n += 256) {
        fp16* dh = gnH + ((size_t)b*HW + n) * 512 + g*CPG;
        #pragma unroll
        for (int cl = 0; cl < CPG; cl += 2) {
            float v0 = (xp[cl*HW + n]     - mean) * rstd * gm[cl]   + bt[cl];
            float v1 = (xp[(cl+1)*HW + n] - mean) * rstd * gm[cl+1] + bt[cl+1];
            v0 = v0 / (1.f + __expf(-v0));
            v1 = v1 / (1.f + __expf(-v1));
            storeH2(dh + cl, v0, v1);
        }
    }
}

// ---------------------------------------------------------------------------
// Row-sum of exp'd scores -> invL per row. One warp per row, shfl only.
// ---------------------------------------------------------------------------
__global__ __launch_bounds__(256) void rowsum_kernel(
    const fp16* __restrict__ e, float* __restrict__ invL)
{
    int w = threadIdx.x >> 5, lane = threadIdx.x & 31;
    size_t row = (size_t)blockIdx.x * 8 + w;
    const half2* sp = (const half2*)(e + row * HW);

    float sum = 0.f;
    #pragma unroll
    for (int i = 0; i < 16; i++) {
        float2 v = __half22float2(sp[i*32 + lane]);
        sum += v.x + v.y;
    }
    #pragma unroll
    for (int o = 16; o; o >>= 1) sum += __shfl_xor_sync(0xffffffffu, sum, o);
    if (lane == 0) invL[row] = 1.f / sum;
}

// ---------------------------------------------------------------------------
// HMMA GEMM, pure fp16. CTA 128x128, 4 warps (2x2), warp tile 64x64, K-chunk
// 64, 3-stage cp.async pipeline with multistage tail scheduling + fragment
// double buffering, static persistent tile chaining (pow2 addressing).
// EPI: 0=QK(q pre-scaled by scale*log2e)  1=V  2=SCORES->exp2->attn  3=AV(/L)
//      4=OUT
// ---------------------------------------------------------------------------
#define KC       64
#define OPB      16384
#define STAGE_B  (2*OPB)
#define SMEM_BYTES (3*STAGE_B)
#define NPERS    296

template<int LOG_NCH>
__device__ __forceinline__ void load_stage(uint32_t dst, const fp16* Ap, const fp16* Bp,
                                           int tid)
{
    constexpr int Kb = KC << LOG_NCH;
    #pragma unroll
    for (int it = 0; it < 8; it++) {
        int e   = it*128 + tid;
        int row = e >> 3, grp = e & 7;
        uint32_t off = (uint32_t)(row*128 + ((grp ^ (row & 7)) << 4));
        cpasync16(dst + off,       Ap + (size_t)row * Kb + grp*8);
        cpasync16(dst + OPB + off, Bp + (size_t)row * Kb + grp*8);
    }
}

// EPI, log2(nch), log2(ntn), log2(per_b)
template<int EPI, int LOG_NCH, int LOG_NTN, int LOG_PERB>
__global__ __launch_bounds__(128, 2) void hmma_gemm(
    const fp16* __restrict__ AH, size_t aStr,
    const fp16* __restrict__ BH, size_t bStr,
    const float* __restrict__ bias, const float* __restrict__ bias2,
    const float* __restrict__ xres, const float* __restrict__ invL,
    float* __restrict__ fOut, fp16* __restrict__ oH, fp16* __restrict__ o2H,
    float scale, int ntiles)
{
    constexpr int nch = 1 << LOG_NCH;
    constexpr int Kb  = KC << LOG_NCH;
    extern __shared__ char smem[];
    const uint32_t sbase = smem_u32(smem);
    const int tid  = threadIdx.x;
    const int lane = tid & 31, wid = tid >> 5;
    const int wm = wid >> 1, wn = wid & 1;
    const int bx = blockIdx.x;
    const int G  = (int)gridDim.x;

    const int my_n = (bx < ntiles) ? ((ntiles - 1 - bx) / G + 1) : 0;
    if (my_n == 0) return;
    const int total = my_n << LOG_NCH;

    auto tileA = [&](int tile) -> const fp16* {
        int bz  = tile >> LOG_PERB;
        int rem = tile & ((1 << LOG_PERB) - 1);
        int m0  = (rem >> LOG_NTN) << 7;
        return AH + (size_t)bz*aStr + (size_t)m0 * Kb;
    };
    auto tileB = [&](int tile) -> const fp16* {
        int bz  = tile >> LOG_PERB;
        int rem = tile & ((1 << LOG_PERB) - 1);
        int n0  = (rem & ((1 << LOG_NTN) - 1)) << 7;
        return BH + (size_t)bz*bStr + (size_t)n0 * Kb;
    };

    const int aR0 = wm*64 + (lane & 15);
    const int aGs = lane >> 4;
    const int bR0 = wn*64 + (lane & 7) + ((lane >> 4) & 1) * 8;
    const int bGs = (lane >> 3) & 1;

    float acc[4][8][4];
    #pragma unroll
    for (int i = 0; i < 4; i++)
        #pragma unroll
        for (int j = 0; j < 8; j++)
            #pragma unroll
            for (int c = 0; c < 4; c++) acc[i][j][c] = 0.f;

    uint32_t afr[2][4][4];
    uint32_t bfr[2][8][2];

    auto frag_load = [&](int bf, uint32_t ab, uint32_t bb, int g) {
        uint32_t gA = (uint32_t)(g + aGs);
        uint32_t gB = (uint32_t)(g + bGs);
        #pragma unroll
        for (int mf = 0; mf < 4; mf++) {
            int r = aR0 + mf*16;
            ldsm4(afr[bf][mf], ab + (uint32_t)(r*128) + ((gA ^ (uint32_t)(r & 7)) << 4));
        }
        #pragma unroll
        for (int p = 0; p < 4; p++) {
            int r = bR0 + p*16;
            uint32_t rr[4];
            ldsm4(rr, bb + (uint32_t)(r*128) + ((gB ^ (uint32_t)(r & 7)) << 4));
            bfr[bf][2*p][0]   = rr[0]; bfr[bf][2*p][1]   = rr[1];
            bfr[bf][2*p+1][0] = rr[2]; bfr[bf][2*p+1][1] = rr[3];
        }
    };

    const fp16* Ac = tileA(bx);
    const fp16* Bc = tileB(bx);

    load_stage<LOG_NCH>(sbase,           Ac,      Bc,      tid);  CP_COMMIT();
    load_stage<LOG_NCH>(sbase + STAGE_B, Ac + KC, Bc + KC, tid);  CP_COMMIT();
    CP_WAIT1();
    __syncthreads();
    frag_load(0, sbase, sbase + OPB, 0);

    int stage = 0;
    #pragma unroll 1
    for (int i = 0; i < my_n; i++) {
        const int tile = bx + i*G;
        #pragma unroll 1
        for (int t = 0; t < nch; t++) {
            const int g = (i << LOG_NCH) + t;
            const uint32_t abase = sbase + stage*STAGE_B;
            const uint32_t bbase = abase + OPB;
            int sN = stage + 1; if (sN == 3) sN = 0;
            int s2 = stage + 2; if (s2 >= 3) s2 -= 3;

            #pragma unroll
            for (int step = 0; step < 4; step++) {
                int cur = step & 1, nxt = cur ^ 1;
                if (step == 0 && g + 2 < total) {
                    int gp = g + 2;
                    int ip = gp >> LOG_NCH;
                    int cp = gp & (nch - 1);
                    const fp16* Ap; const fp16* Bp;
                    if (ip == i) { Ap = Ac + cp*KC; Bp = Bc + cp*KC; }
                    else {
                        int tl = bx + ip*G;
                        Ap = tileA(tl) + cp*KC;
                        Bp = tileB(tl) + cp*KC;
                    }
                    load_stage<LOG_NCH>(sbase + s2*STAGE_B, Ap, Bp, tid);
                    CP_COMMIT();
                }
                if (step < 3) {
                    frag_load(nxt, abase, bbase, (step+1)*2);
                } else {
                    if (g + 2 < total) CP_WAIT1(); else CP_WAIT0();
                    __syncthreads();
                    if (g + 1 < total) {
                        uint32_t nab = sbase + sN*STAGE_B;
                        frag_load(nxt, nab, nab + OPB, 0);
                    }
                }
                #pragma unroll
                for (int mf = 0; mf < 4; mf++)
                    #pragma unroll
                    for (int nf = 0; nf < 8; nf++)
                        mma16816(acc[mf][nf], afr[cur][mf], bfr[cur][nf]);
            }
            stage = sN;
        }

        // ---------------- epilogue for tile ----------------
        {
            int bz  = tile >> LOG_PERB;
            int rem = tile & ((1 << LOG_PERB) - 1);
            int m0  = (rem >> LOG_NTN) << 7;
            int n0  = (rem & ((1 << LOG_NTN) - 1)) << 7;
            const int tr = lane >> 2;
            const int tc = (lane & 3) * 2;

            #pragma unroll
            for (int mf = 0; mf < 4; mf++) {
                #pragma unroll
                for (int half = 0; half < 2; half++) {
                    int r = m0 + wm*64 + mf*16 + tr + half*8;
                    float iL = 0.f;
                    if (EPI == 3) iL = invL[(size_t)bz*HW + r];
                    #pragma unroll
                    for (int nf = 0; nf < 8; nf++) {
                        int c = n0 + wn*64 + nf*8 + tc;
                        float d0 = acc[mf][nf][half*2 + 0];
                        float d1 = acc[mf][nf][half*2 + 1];

                        if (EPI == 0) {                 // QK: q pre-scaled
                            if (c < 512) {
                                d0 = (d0 + bias[c])   * scale;
                                d1 = (d1 + bias[c+1]) * scale;
                                size_t idx = ((size_t)bz*HW + r) * 512 + c;
                                storeH2(oH + idx, d0, d1);
                            } else {
                                d0 += bias2[c-512]; d1 += bias2[c-511];
                                size_t idx = ((size_t)bz*HW + r) * 512 + (c - 512);
                                storeH2(o2H + idx, d0, d1);
                            }
                        } else if (EPI == 1) {          // V: D[ch][i]
                            float bb = bias[r];
                            size_t idx = ((size_t)bz*CC + r) * HW + c;
                            storeH2(oH + idx, d0+bb, d1+bb);
                        } else if (EPI == 2) {          // scores -> exp2 -> attn
                            size_t idx = ((size_t)bz*HW + r) * HW + c;
                            storeH2(oH + idx, ex2(d0), ex2(d1));
                        } else if (EPI == 3) {          // AV, normalize by invL
                            size_t idx = ((size_t)bz*HW + r) * 512 + c;
                            storeH2(oH + idx, d0*iL, d1*iL);
                        } else {                        // OUT: + bias + residual
                            float bb = bias[r];
                            size_t off = ((size_t)bz*CC + r) * HW + c;
                            float2 xr = *(const float2*)(xres + off);
                            *(float2*)(fOut + off) = make_float2(d0+bb+xr.x, d1+bb+xr.y);
                        }
                    }
                }
            }
            #pragma unroll
            for (int ii = 0; ii < 4; ii++)
                #pragma unroll
                for (int jj = 0; jj < 8; jj++)
                    #pragma unroll
                    for (int cc = 0; cc < 4; cc++) acc[ii][jj][cc] = 0.f;
        }

        if (i + 1 < my_n) {
            Ac = tileA(bx + (i+1)*G);
            Bc = tileB(bx + (i+1)*G);
        }
    }
}

// ---------------------------------------------------------------------------
extern "C" void kernel_launch(void* const* d_in, const int* in_sizes, int n_in,
                              void* d_out, int out_size)
{
    const float* x     = (const float*)d_in[0];
    const float* Wq    = (const float*)d_in[1];
    const float* bq    = (const float*)d_in[2];
    const float* Wk    = (const float*)d_in[3];
    const float* bk    = (const float*)d_in[4];
    const float* Wv    = (const float*)d_in[5];
    const float* bv    = (const float*)d_in[6];
    const float* Wo    = (const float*)d_in[7];
    const float* bo    = (const float*)d_in[8];
    const float* gamma = (const float*)d_in[9];
    const float* beta  = (const float*)d_in[10];
    float* out = (float*)d_out;

    unsigned char* base = nullptr;
    cudaGetSymbolAddress((void**)&base, g_scratch);
    fp16*  WH  = (fp16*)(base + OFF_WH);
    fp16*  gnH = (fp16*)(base + OFF_GNH);
    fp16*  qH  = (fp16*)(base + OFF_QH);
    fp16*  kH  = (fp16*)(base + OFF_KH);
    fp16*  vH  = (fp16*)(base + OFF_VH);
    fp16*  aH  = (fp16*)(base + OFF_AH);
    fp16*  hhH = (fp16*)(base + OFF_HHH);
    float* Lv  = (float*)(base + OFF_L);

    cudaFuncSetAttribute((const void*)hmma_gemm<0,3,3,6>, cudaFuncAttributeMaxDynamicSharedMemorySize, SMEM_BYTES);
    cudaFuncSetAttribute((const void*)hmma_gemm<1,3,3,5>, cudaFuncAttributeMaxDynamicSharedMemorySize, SMEM_BYTES);
    cudaFuncSetAttribute((const void*)hmma_gemm<2,3,3,6>, cudaFuncAttributeMaxDynamicSharedMemorySize, SMEM_BYTES);
    cudaFuncSetAttribute((const void*)hmma_gemm<3,4,2,5>, cudaFuncAttributeMaxDynamicSharedMemorySize, SMEM_BYTES);
    cudaFuncSetAttribute((const void*)hmma_gemm<4,3,3,5>, cudaFuncAttributeMaxDynamicSharedMemorySize, SMEM_BYTES);

    // q pre-multiplied by scale * log2(e) so scores epilogue is exp2(D)
    const float scq = (1.0f / sqrtf((float)CC)) * 1.44269504f;
    const size_t PXS = (size_t)HW * 512;
    const size_t CHS = (size_t)CC * HW;

    convert_w_kernel<<<2048, 256>>>(Wq, Wk, Wv, Wo, WH);
    gn_silu_kernel<<<BB*GG, 256>>>(x, gamma, beta, gnH);

    // QK: M=1024 pixels (A=gn), N=1024 q|k rows (B=W), K=512. 1024 tiles.
    hmma_gemm<0,3,3,6><<<NPERS, 128, SMEM_BYTES>>>(
        gnH, PXS, WH, 0, bq, bk, nullptr, nullptr, nullptr, qH, kH, scq, 64*BB);

    // V: M=512 ch (A=Wv), N=1024 px (B=gn), K=512. 512 tiles.
    hmma_gemm<1,3,3,5><<<NPERS, 128, SMEM_BYTES>>>(
        WH + (size_t)1024*512, 0, gnH, PXS, bv, nullptr, nullptr, nullptr,
        nullptr, vH, nullptr, 0.f, 32*BB);

    // scores: M=1024 i (A=q'), N=1024 j (B=k), K=512 -> exp2 -> attn. 1024 tiles.
    hmma_gemm<2,3,3,6><<<NPERS, 128, SMEM_BYTES>>>(
        qH, PXS, kH, PXS, nullptr, nullptr, nullptr, nullptr,
        nullptr, aH, nullptr, 0.f, 64*BB);

    rowsum_kernel<<<BB*HW/8, 256>>>(aH, Lv);

    // AV: M=1024 i (A=attn_unnorm), N=512 ch (B=v), K=1024, /L. 512 tiles.
    hmma_gemm<3,4,2,5><<<NPERS, 128, SMEM_BYTES>>>(
        aH, (size_t)HW*HW, vH, CHS, nullptr, nullptr, nullptr, Lv,
        nullptr, hhH, nullptr, 0.f, 32*BB);

    // OUT: M=512 ch (A=Wo), N=1024 i (B=hh), K=512, +bo +x. 512 tiles.
    hmma_gemm<4,3,3,5><<<NPERS, 128, SMEM_BYTES>>>(
        WH + (size_t)1536*512, 0, hhH, PXS, bo, nullptr, x, nullptr,
        out, nullptr, nullptr, 0.f, 32*BB);
}